// round 15
// baseline (speedup 1.0000x reference)
#include <cuda_runtime.h>
#include <cuda_fp16.h>
#include <mma.h>
#include <math.h>
#include <cstdint>

using namespace nvcuda;

#define BSZ     8
#define QL      16
#define TOK     128
#define DIM     4096
#define NKV     8
#define HD      128
#define MAXSEQ  4096
#define STARTP  4080
#define KVLEN   4096
#define QKV_N   6144
#define NBG     64
#define NSPLIT  4
#define KVSPLIT 1024
#define LT      128
#define NT_FL   (KVSPLIT / LT)
#define SPLITQ  8
#define SPLITO  8
#define NTHR    512

__device__ float g_qkv[TOK * QKV_N];
__device__ float g_qkvp[SPLITQ * TOK * QKV_N];
__device__ float g_op[SPLITO * TOK * DIM];
__device__ float g_pvp[NSPLIT * NBG * 64 * HD];
__device__ float g_rsum[NSPLIT * NBG * 64];
__device__ float g_att[TOK * DIM];

typedef wmma::fragment<wmma::accumulator, 16, 16, 16, float> HC;
typedef wmma::fragment<wmma::accumulator, 16, 16, 16, __half> HCH;
typedef wmma::fragment<wmma::matrix_a, 16, 16, 16, __half, wmma::row_major> HA;
typedef wmma::fragment<wmma::matrix_b, 16, 16, 16, __half, wmma::row_major> HB;
typedef wmma::fragment<wmma::matrix_b, 16, 16, 16, __half, wmma::col_major> HBT;

__device__ __forceinline__ uint4 f8h8(float4 a, float4 b) {
    __half2 h0 = __floats2half2_rn(a.x, a.y);
    __half2 h1 = __floats2half2_rn(a.z, a.w);
    __half2 h2 = __floats2half2_rn(b.x, b.y);
    __half2 h3 = __floats2half2_rn(b.z, b.w);
    uint4 r;
    r.x = *(uint32_t*)&h0; r.y = *(uint32_t*)&h1;
    r.z = *(uint32_t*)&h2; r.w = *(uint32_t*)&h3;
    return r;
}

__device__ __forceinline__ float ex2f(float x) {
    float r;
    asm("ex2.approx.f32 %0, %1;" : "=f"(r) : "f"(x));
    return r;
}

// ------------- 128x128 split-K fp16 GEMM body, 512 thr, warp 32x32 -------------
// (R10-proven shape; chosen for wave balance / partial traffic, not tile size)
#define SMEM_GEMM (2 * 128 * 40 * 2 + 2 * 32 * 136 * 2)

#define GEMM_BODY(Abase, LDAG, Bbase, LDBG, CPART, LDC, NCHUNK)                    \
    extern __shared__ __half smg[];                                                \
    __half* Asb[2] = {smg, smg + 128 * 40};                                        \
    __half* Bsb[2] = {smg + 2 * 128 * 40, smg + 2 * 128 * 40 + 32 * 136};          \
    const int tid = threadIdx.x;                                                   \
    const int wid = tid >> 5, wr = wid >> 2, wcx = wid & 3;                        \
    const int am = tid >> 2, ak = (tid & 3) << 3;   /* A: 128 x 32 */              \
    const int bk = tid >> 4, bn = (tid & 15) << 3;  /* B: 32 x 128 */              \
    HC acc[2][2];                                                                  \
    _Pragma("unroll")                                                              \
    for (int i = 0; i < 2; i++)                                                    \
        _Pragma("unroll")                                                          \
        for (int j = 0; j < 2; j++) wmma::fill_fragment(acc[i][j], 0.0f);          \
    float4 ra0, ra1, rb0, rb1;                                                     \
    ra0 = *(const float4*)((Abase) + (size_t)am * (LDAG) + ak);                    \
    ra1 = *(const float4*)((Abase) + (size_t)am * (LDAG) + ak + 4);                \
    rb0 = *(const float4*)((Bbase) + (size_t)bk * (LDBG) + bn);                    \
    rb1 = *(const float4*)((Bbase) + (size_t)bk * (LDBG) + bn + 4);                \
    *(uint4*)(&Asb[0][am * 40 + ak]) = f8h8(ra0, ra1);                             \
    *(uint4*)(&Bsb[0][bk * 136 + bn]) = f8h8(rb0, rb1);                            \
    __syncthreads();                                                               \
    for (int t = 0; t < (NCHUNK); t++) {                                           \
        int cur = t & 1;                                                           \
        if (t + 1 < (NCHUNK)) {                                                    \
            ra0 = *(const float4*)((Abase) + (size_t)am * (LDAG) + (t + 1) * 32 + ak); \
            ra1 = *(const float4*)((Abase) + (size_t)am * (LDAG) + (t + 1) * 32 + ak + 4); \
            rb0 = *(const float4*)((Bbase) + (size_t)((t + 1) * 32 + bk) * (LDBG) + bn); \
            rb1 = *(const float4*)((Bbase) + (size_t)((t + 1) * 32 + bk) * (LDBG) + bn + 4); \
        }                                                                          \
        _Pragma("unroll")                                                          \
        for (int kk = 0; kk < 32; kk += 16) {                                      \
            HA a[2]; HB b[2];                                                      \
            _Pragma("unroll")                                                      \
            for (int i = 0; i < 2; i++)                                            \
                wmma::load_matrix_sync(a[i], Asb[cur] + (wr * 32 + i * 16) * 40 + kk, 40); \
            _Pragma("unroll")                                                      \
            for (int j = 0; j < 2; j++)                                            \
                wmma::load_matrix_sync(b[j], Bsb[cur] + kk * 136 + wcx * 32 + j * 16, 136); \
            _Pragma("unroll")                                                      \
            for (int i = 0; i < 2; i++)                                            \
                _Pragma("unroll")                                                  \
                for (int j = 0; j < 2; j++)                                        \
                    wmma::mma_sync(acc[i][j], a[i], b[j], acc[i][j]);              \
        }                                                                          \
        if (t + 1 < (NCHUNK)) {                                                    \
            *(uint4*)(&Asb[1 - cur][am * 40 + ak]) = f8h8(ra0, ra1);               \
            *(uint4*)(&Bsb[1 - cur][bk * 136 + bn]) = f8h8(rb0, rb1);              \
        }                                                                          \
        __syncthreads();                                                           \
    }                                                                              \
    _Pragma("unroll")                                                              \
    for (int i = 0; i < 2; i++)                                                    \
        _Pragma("unroll")                                                          \
        for (int j = 0; j < 2; j++)                                                \
            wmma::store_matrix_sync((CPART) + (size_t)(wr * 32 + i * 16) * (LDC) + wcx * 32 + j * 16, \
                                    acc[i][j], (LDC), wmma::mem_row_major);

// ---------------- kernel 1: QKV GEMM split-K(8), grid (48,8) -------------------
__global__ void __launch_bounds__(NTHR) qkv_kernel(
    const float* __restrict__ x,
    const float* __restrict__ Wq, const float* __restrict__ Wk,
    const float* __restrict__ Wv)
{
    const int n0 = blockIdx.x * 128;
    const int kb = blockIdx.y * (DIM / SPLITQ);
    const float* B; int ldb, col;
    if (n0 < 4096)      { B = Wq; ldb = 4096; col = n0; }
    else if (n0 < 5120) { B = Wk; ldb = 1024; col = n0 - 4096; }
    else                { B = Wv; ldb = 1024; col = n0 - 5120; }

    const float* Abase = x + kb;
    const float* Bbase = B + (size_t)kb * ldb + col;
    float* Cpart = g_qkvp + (size_t)blockIdx.y * TOK * QKV_N + n0;
    GEMM_BODY(Abase, DIM, Bbase, ldb, Cpart, QKV_N, DIM / SPLITQ / 32)
}

__global__ void qkv_reduce_kernel()
{
    int i4 = (blockIdx.x * 256 + threadIdx.x) * 4;
    float4 s = make_float4(0.f, 0.f, 0.f, 0.f);
#pragma unroll
    for (int sp = 0; sp < SPLITQ; sp++) {
        float4 v = *(const float4*)(g_qkvp + (size_t)sp * TOK * QKV_N + i4);
        s.x += v.x; s.y += v.y; s.z += v.z; s.w += v.w;
    }
    *(float4*)(g_qkv + i4) = s;
}

// ---------------- kernel 2: flash attention fp16 (R13 structure, verbatim) -----
#define SMEM_FLASH ((64*136 + 128*136 + 64*136) * 2 + (64 + 512) * 4)

__global__ void __launch_bounds__(NTHR, 2) flash_kernel(
    const float* __restrict__ k_cache, const float* __restrict__ v_cache,
    const float* __restrict__ bq, const float* __restrict__ bk,
    const float* __restrict__ bv)
{
    extern __shared__ char smc[];
    __half* Qs   = (__half*)smc;                          // [64][136]
    __half* KVs  = Qs + 64 * 136;                         // [128][136]
    __half* Ps   = KVs + 128 * 136;                       // [64][136]
    float* rowsum = (float*)(Ps + 64 * 136);              // [64]
    float* tmp    = rowsum + 64;                          // [8][64]

    const int split = blockIdx.x;
    const int bg = blockIdx.y, b = bg >> 3, g = bg & 7;
    const int tid = threadIdx.x, wid = tid >> 5;
    const int wr4 = wid >> 2, wc4 = wid & 3;
    const float scale = 0.08838834764831845f * 1.4426950408889634f;  // log2 domain

    const int qm0 = tid >> 4;
    const int qc8 = (tid & 15) << 3;
#pragma unroll
    for (int i = 0; i < 2; i++) {
        int m = qm0 + 32 * i;
        int r = m >> 4, s = m & 15;
        int hcol = (g * 4 + r) * HD + qc8;
        const float* qp = g_qkv + (size_t)(b * 16 + s) * QKV_N + hcol;
        float4 q0 = *(const float4*)(qp);
        float4 q1 = *(const float4*)(qp + 4);
        float4 b0 = *(const float4*)(bq + hcol);
        float4 b1 = *(const float4*)(bq + hcol + 4);
        q0.x = (q0.x + b0.x) * scale; q0.y = (q0.y + b0.y) * scale;
        q0.z = (q0.z + b0.z) * scale; q0.w = (q0.w + b0.w) * scale;
        q1.x = (q1.x + b1.x) * scale; q1.y = (q1.y + b1.y) * scale;
        q1.z = (q1.z + b1.z) * scale; q1.w = (q1.w + b1.w) * scale;
        *(uint4*)(&Qs[m * 136 + qc8]) = f8h8(q0, q1);
    }
    if (tid < 64) rowsum[tid] = 0.f;

    HC acc_o[2];
#pragma unroll
    for (int j = 0; j < 2; j++) wmma::fill_fragment(acc_o[j], 0.0f);

    const int row = tid & 63, qq = tid >> 6;

#define STAGE_KV(l0, qoff, cache, bias)                                            \
    _Pragma("unroll")                                                              \
    for (int i = 0; i < 4; i++) {                                                  \
        int slot = tid + i * 512;                                                  \
        int l = slot >> 4;                                                         \
        int c8 = (slot & 15) << 3;                                                 \
        int lg = (l0) + l;                                                         \
        float4 c0, c1;                                                             \
        if (lg >= STARTP) {                                                        \
            const float* sp_ = g_qkv + (size_t)(b * 16 + (lg - STARTP)) * QKV_N    \
                               + (qoff) + g * HD + c8;                             \
            c0 = *(const float4*)(sp_); c1 = *(const float4*)(sp_ + 4);            \
            float4 b0 = *(const float4*)((bias) + g * HD + c8);                    \
            float4 b1 = *(const float4*)((bias) + g * HD + c8 + 4);                \
            c0.x += b0.x; c0.y += b0.y; c0.z += b0.z; c0.w += b0.w;                \
            c1.x += b1.x; c1.y += b1.y; c1.z += b1.z; c1.w += b1.w;                \
        } else {                                                                   \
            const float* sp_ = (cache) + (((size_t)b * MAXSEQ + lg) * NKV + g) * HD + c8; \
            c0 = *(const float4*)(sp_); c1 = *(const float4*)(sp_ + 4);            \
        }                                                                          \
        *(uint4*)(&KVs[l * 136 + c8]) = f8h8(c0, c1);                              \
    }

    const int lbase0 = split * KVSPLIT;

    for (int t = 0; t < NT_FL; t++) {
        const int l0 = lbase0 + t * LT;

        STAGE_KV(l0, 4096, k_cache, bk)
        __syncthreads();

        // S = Q @ K^T (log2 domain) : 64x128, k=128; warp tile 16x32
        HC acc_s[2];
        wmma::fill_fragment(acc_s[0], 0.0f);
        wmma::fill_fragment(acc_s[1], 0.0f);
#pragma unroll
        for (int kk = 0; kk < HD; kk += 16) {
            HA a;
            wmma::load_matrix_sync(a, Qs + (wr4 * 16) * 136 + kk, 136);
#pragma unroll
            for (int j = 0; j < 2; j++) {
                HBT bt;
                wmma::load_matrix_sync(bt, KVs + (wc4 * 32 + j * 16) * 136 + kk, 136);
                wmma::mma_sync(acc_s[j], a, bt, acc_s[j]);
            }
        }
        // exp in registers (fp32 input), convert to half fragment, store to Ps
        HCH ph[2];
#pragma unroll
        for (int j = 0; j < 2; j++) {
#pragma unroll
            for (int e = 0; e < acc_s[j].num_elements; e++)
                ph[j].x[e] = __float2half(ex2f(acc_s[j].x[e]));
            wmma::store_matrix_sync(Ps + (wr4 * 16) * 136 + wc4 * 32 + j * 16,
                                    ph[j], 136, wmma::mem_row_major);
        }
        __syncthreads();   // KVs reads done; Ps visible

        STAGE_KV(l0, 5120, v_cache, bv)       // V into KVs
        {
            const uint4 p0 = *(const uint4*)(&Ps[row * 136 + qq * 16]);
            const uint4 p1 = *(const uint4*)(&Ps[row * 136 + qq * 16 + 8]);
            const uint32_t w[8] = {p0.x, p0.y, p0.z, p0.w, p1.x, p1.y, p1.z, p1.w};
            float part = 0.f;
#pragma unroll
            for (int j = 0; j < 8; j++) {
                float2 f = __half22float2(*(const __half2*)&w[j]);
                part += f.x + f.y;
            }
            tmp[qq * 64 + row] = part;
        }
        __syncthreads();

        if (tid < 64) {
            float s = 0.f;
#pragma unroll
            for (int q8 = 0; q8 < 8; q8++) s += tmp[q8 * 64 + tid];
            rowsum[tid] += s;
        }

        // O += P @ V : 64x128, k=128; warp tile 16x32
#pragma unroll
        for (int kk = 0; kk < LT; kk += 16) {
            HA a;
            wmma::load_matrix_sync(a, Ps + (wr4 * 16) * 136 + kk, 136);
#pragma unroll
            for (int j = 0; j < 2; j++) {
                HB bfr;
                wmma::load_matrix_sync(bfr, KVs + kk * 136 + wc4 * 32 + j * 16, 136);
                wmma::mma_sync(acc_o[j], a, bfr, acc_o[j]);
            }
        }
        __syncthreads();
    }

#pragma unroll
    for (int j = 0; j < 2; j++)
        wmma::store_matrix_sync(
            g_pvp + ((size_t)(split * NBG + bg) * 64 + wr4 * 16) * HD + wc4 * 32 + j * 16,
            acc_o[j], HD, wmma::mem_row_major);
    if (tid < 64)
        g_rsum[(size_t)(split * NBG + bg) * 64 + tid] = rowsum[tid];
}

// ---------------- combine splits, normalize, remap -----------------------------
__global__ void flash_combine_kernel()
{
    int t = blockIdx.x * 256 + threadIdx.x;
    int rowg = t >> 5;
    int c4 = (t & 31) << 2;
    float4 s = make_float4(0.f, 0.f, 0.f, 0.f);
    float den = 0.f;
#pragma unroll
    for (int sp = 0; sp < NSPLIT; sp++) {
        float4 v = *(const float4*)(g_pvp + ((size_t)sp * NBG * 64 + rowg) * HD + c4);
        s.x += v.x; s.y += v.y; s.z += v.z; s.w += v.w;
        den += g_rsum[(size_t)sp * NBG * 64 + rowg];
    }
    float inv = 1.f / den;
    s.x *= inv; s.y *= inv; s.z *= inv; s.w *= inv;
    int bg = rowg >> 6, qr = rowg & 63;
    int b = bg >> 3, g = bg & 7, r = qr >> 4, sq = qr & 15;
    *(float4*)(g_att + (size_t)(b * 16 + sq) * DIM + (g * 4 + r) * HD + c4) = s;
}

// ---------------- kernel 4: O projection split-K(8), grid (32,8) ---------------
__global__ void __launch_bounds__(NTHR) o_kernel(const float* __restrict__ Wo)
{
    const int n0 = blockIdx.x * 128;
    const int kb = blockIdx.y * (DIM / SPLITO);
    const float* Abase = g_att + kb;
    const float* Bbase = Wo + (size_t)kb * DIM + n0;
    float* Cpart = g_op + (size_t)blockIdx.y * TOK * DIM + n0;
    GEMM_BODY(Abase, DIM, Bbase, DIM, Cpart, DIM, DIM / SPLITO / 32)
}

__global__ void o_reduce_kernel(float* __restrict__ out, const float* __restrict__ bo)
{
    int i4 = (blockIdx.x * 256 + threadIdx.x) * 4;
    int n = i4 & (DIM - 1);
    float4 s = *(const float4*)(bo + n);
#pragma unroll
    for (int sp = 0; sp < SPLITO; sp++) {
        float4 v = *(const float4*)(g_op + (size_t)sp * TOK * DIM + i4);
        s.x += v.x; s.y += v.y; s.z += v.z; s.w += v.w;
    }
    *(float4*)(out + i4) = s;
}

// ---------------- launch ----------------------------------------------------------
extern "C" void kernel_launch(void* const* d_in, const int* in_sizes, int n_in,
                              void* d_out, int out_size)
{
    const float* x  = (const float*)d_in[0];
    const float* kc = (const float*)d_in[1];
    const float* vc = (const float*)d_in[2];
    const float* Wq = (const float*)d_in[3];  const float* bq = (const float*)d_in[4];
    const float* Wk = (const float*)d_in[5];  const float* bk = (const float*)d_in[6];
    const float* Wv = (const float*)d_in[7];  const float* bv = (const float*)d_in[8];
    const float* Wo = (const float*)d_in[9];  const float* bo = (const float*)d_in[10];
    float* out = (float*)d_out;

    cudaFuncSetAttribute(flash_kernel,
                         cudaFuncAttributeMaxDynamicSharedMemorySize, SMEM_FLASH);
    cudaFuncSetAttribute(qkv_kernel,
                         cudaFuncAttributeMaxDynamicSharedMemorySize, SMEM_GEMM);
    cudaFuncSetAttribute(o_kernel,
                         cudaFuncAttributeMaxDynamicSharedMemorySize, SMEM_GEMM);

    qkv_kernel<<<dim3(48, SPLITQ), NTHR, SMEM_GEMM>>>(x, Wq, Wk, Wv);
    qkv_reduce_kernel<<<TOK * QKV_N / 1024, 256>>>();
    flash_kernel<<<dim3(NSPLIT, NBG), NTHR, SMEM_FLASH>>>(kc, vc, bq, bk, bv);
    flash_combine_kernel<<<512, 256>>>();
    o_kernel<<<dim3(32, SPLITO), NTHR, SMEM_GEMM>>>(Wo);
    o_reduce_kernel<<<512, 256>>>(out, bo);
}

// round 16
// speedup vs baseline: 1.1153x; 1.1153x over previous
#include <cuda_runtime.h>
#include <cuda_fp16.h>
#include <mma.h>
#include <math.h>
#include <cstdint>

using namespace nvcuda;

#define BSZ     8
#define QL      16
#define TOK     128
#define DIM     4096
#define NKV     8
#define HD      128
#define MAXSEQ  4096
#define STARTP  4080
#define KVLEN   4096
#define QKV_N   6144
#define NBG     64
#define NSPLIT  4
#define KVSPLIT 1024
#define LT      128
#define NT_FL   (KVSPLIT / LT)
#define SPLITQ  8
#define SPLITO  8
#define NTHR    512

__device__ float g_qkv[TOK * QKV_N];
__device__ float g_qkvp[SPLITQ * TOK * QKV_N];
__device__ float g_op[SPLITO * TOK * DIM];
__device__ float g_pvp[NSPLIT * NBG * 64 * HD];
__device__ float g_rsum[NSPLIT * NBG * 64];
__device__ float g_att[TOK * DIM];

typedef wmma::fragment<wmma::accumulator, 16, 16, 16, float> HC;
typedef wmma::fragment<wmma::accumulator, 16, 16, 16, __half> HCH;
typedef wmma::fragment<wmma::matrix_a, 16, 16, 16, __half, wmma::row_major> HA;
typedef wmma::fragment<wmma::matrix_b, 16, 16, 16, __half, wmma::row_major> HB;
typedef wmma::fragment<wmma::matrix_b, 16, 16, 16, __half, wmma::col_major> HBT;

__device__ __forceinline__ uint4 f8h8(float4 a, float4 b) {
    __half2 h0 = __floats2half2_rn(a.x, a.y);
    __half2 h1 = __floats2half2_rn(a.z, a.w);
    __half2 h2 = __floats2half2_rn(b.x, b.y);
    __half2 h3 = __floats2half2_rn(b.z, b.w);
    uint4 r;
    r.x = *(uint32_t*)&h0; r.y = *(uint32_t*)&h1;
    r.z = *(uint32_t*)&h2; r.w = *(uint32_t*)&h3;
    return r;
}

__device__ __forceinline__ float ex2f(float x) {
    float r;
    asm("ex2.approx.f32 %0, %1;" : "=f"(r) : "f"(x));
    return r;
}

// ------------- 128x256 split-K fp16 GEMM body, 512 thr, warp 32x64 -------------
#define SMEM_GEMM (2 * 128 * 40 * 2 + 2 * 32 * 264 * 2)

#define GEMM_BODY(Abase, LDAG, Bbase, LDBG, CPART, LDC, NCHUNK)                    \
    extern __shared__ __half smg[];                                                \
    __half* Asb[2] = {smg, smg + 128 * 40};                                        \
    __half* Bsb[2] = {smg + 2 * 128 * 40, smg + 2 * 128 * 40 + 32 * 264};          \
    const int tid = threadIdx.x;                                                   \
    const int wid = tid >> 5, wr = wid >> 2, wcx = wid & 3;                        \
    const int am = tid >> 2, ak = (tid & 3) << 3;                                  \
    const int bs0 = tid, bs1 = tid + 512;                                          \
    const int br0 = bs0 >> 5, bc0 = (bs0 & 31) << 3;                               \
    const int br1 = bs1 >> 5, bc1 = (bs1 & 31) << 3;                               \
    HC acc[2][4];                                                                  \
    _Pragma("unroll")                                                              \
    for (int i = 0; i < 2; i++)                                                    \
        _Pragma("unroll")                                                          \
        for (int j = 0; j < 4; j++) wmma::fill_fragment(acc[i][j], 0.0f);          \
    float4 ra0, ra1, rb00, rb01, rb10, rb11;                                       \
    ra0 = *(const float4*)((Abase) + (size_t)am * (LDAG) + ak);                    \
    ra1 = *(const float4*)((Abase) + (size_t)am * (LDAG) + ak + 4);                \
    rb00 = *(const float4*)((Bbase) + (size_t)br0 * (LDBG) + bc0);                 \
    rb01 = *(const float4*)((Bbase) + (size_t)br0 * (LDBG) + bc0 + 4);             \
    rb10 = *(const float4*)((Bbase) + (size_t)br1 * (LDBG) + bc1);                 \
    rb11 = *(const float4*)((Bbase) + (size_t)br1 * (LDBG) + bc1 + 4);             \
    *(uint4*)(&Asb[0][am * 40 + ak]) = f8h8(ra0, ra1);                             \
    *(uint4*)(&Bsb[0][br0 * 264 + bc0]) = f8h8(rb00, rb01);                        \
    *(uint4*)(&Bsb[0][br1 * 264 + bc1]) = f8h8(rb10, rb11);                        \
    __syncthreads();                                                               \
    for (int t = 0; t < (NCHUNK); t++) {                                           \
        int cur = t & 1;                                                           \
        if (t + 1 < (NCHUNK)) {                                                    \
            ra0 = *(const float4*)((Abase) + (size_t)am * (LDAG) + (t + 1) * 32 + ak); \
            ra1 = *(const float4*)((Abase) + (size_t)am * (LDAG) + (t + 1) * 32 + ak + 4); \
            rb00 = *(const float4*)((Bbase) + (size_t)((t + 1) * 32 + br0) * (LDBG) + bc0); \
            rb01 = *(const float4*)((Bbase) + (size_t)((t + 1) * 32 + br0) * (LDBG) + bc0 + 4); \
            rb10 = *(const float4*)((Bbase) + (size_t)((t + 1) * 32 + br1) * (LDBG) + bc1); \
            rb11 = *(const float4*)((Bbase) + (size_t)((t + 1) * 32 + br1) * (LDBG) + bc1 + 4); \
        }                                                                          \
        _Pragma("unroll")                                                          \
        for (int kk = 0; kk < 32; kk += 16) {                                      \
            HA a[2];                                                               \
            _Pragma("unroll")                                                      \
            for (int i = 0; i < 2; i++)                                            \
                wmma::load_matrix_sync(a[i], Asb[cur] + (wr * 32 + i * 16) * 40 + kk, 40); \
            _Pragma("unroll")                                                      \
            for (int j = 0; j < 4; j++) {                                          \
                HB b;                                                              \
                wmma::load_matrix_sync(b, Bsb[cur] + kk * 264 + wcx * 64 + j * 16, 264); \
                wmma::mma_sync(acc[0][j], a[0], b, acc[0][j]);                     \
                wmma::mma_sync(acc[1][j], a[1], b, acc[1][j]);                     \
            }                                                                      \
        }                                                                          \
        if (t + 1 < (NCHUNK)) {                                                    \
            *(uint4*)(&Asb[1 - cur][am * 40 + ak]) = f8h8(ra0, ra1);               \
            *(uint4*)(&Bsb[1 - cur][br0 * 264 + bc0]) = f8h8(rb00, rb01);          \
            *(uint4*)(&Bsb[1 - cur][br1 * 264 + bc1]) = f8h8(rb10, rb11);          \
        }                                                                          \
        __syncthreads();                                                           \
    }                                                                              \
    _Pragma("unroll")                                                              \
    for (int i = 0; i < 2; i++)                                                    \
        _Pragma("unroll")                                                          \
        for (int j = 0; j < 4; j++)                                                \
            wmma::store_matrix_sync((CPART) + (size_t)(wr * 32 + i * 16) * (LDC) + wcx * 64 + j * 16, \
                                    acc[i][j], (LDC), wmma::mem_row_major);

// ---------------- kernel 1: QKV GEMM split-K(8), N-tile 256 --------------------
__global__ void __launch_bounds__(NTHR) qkv_kernel(
    const float* __restrict__ x,
    const float* __restrict__ Wq, const float* __restrict__ Wk,
    const float* __restrict__ Wv)
{
    const int n0 = blockIdx.x * 256;
    const int kb = blockIdx.y * (DIM / SPLITQ);
    const float* B; int ldb, col;
    if (n0 < 4096)      { B = Wq; ldb = 4096; col = n0; }
    else if (n0 < 5120) { B = Wk; ldb = 1024; col = n0 - 4096; }
    else                { B = Wv; ldb = 1024; col = n0 - 5120; }

    const float* Abase = x + kb;
    const float* Bbase = B + (size_t)kb * ldb + col;
    float* Cpart = g_qkvp + (size_t)blockIdx.y * TOK * QKV_N + n0;
    GEMM_BODY(Abase, DIM, Bbase, ldb, Cpart, QKV_N, DIM / SPLITQ / 32)
}

__global__ void qkv_reduce_kernel()
{
    int i4 = (blockIdx.x * 256 + threadIdx.x) * 4;
    float4 s = make_float4(0.f, 0.f, 0.f, 0.f);
#pragma unroll
    for (int sp = 0; sp < SPLITQ; sp++) {
        float4 v = *(const float4*)(g_qkvp + (size_t)sp * TOK * QKV_N + i4);
        s.x += v.x; s.y += v.y; s.z += v.z; s.w += v.w;
    }
    *(float4*)(g_qkv + i4) = s;
}

// ---------------- kernel 2: flash attention fp16 (R13 structure, verbatim) -----
#define SMEM_FLASH ((64*136 + 128*136 + 64*136) * 2 + (64 + 512) * 4)

__global__ void __launch_bounds__(NTHR, 2) flash_kernel(
    const float* __restrict__ k_cache, const float* __restrict__ v_cache,
    const float* __restrict__ bq, const float* __restrict__ bk,
    const float* __restrict__ bv)
{
    extern __shared__ char smc[];
    __half* Qs   = (__half*)smc;                          // [64][136]
    __half* KVs  = Qs + 64 * 136;                         // [128][136]
    __half* Ps   = KVs + 128 * 136;                       // [64][136]
    float* rowsum = (float*)(Ps + 64 * 136);              // [64]
    float* tmp    = rowsum + 64;                          // [8][64]

    const int split = blockIdx.x;
    const int bg = blockIdx.y, b = bg >> 3, g = bg & 7;
    const int tid = threadIdx.x, wid = tid >> 5;
    const int wr4 = wid >> 2, wc4 = wid & 3;
    const float scale = 0.08838834764831845f * 1.4426950408889634f;  // log2 domain

    const int qm0 = tid >> 4;
    const int qc8 = (tid & 15) << 3;
#pragma unroll
    for (int i = 0; i < 2; i++) {
        int m = qm0 + 32 * i;
        int r = m >> 4, s = m & 15;
        int hcol = (g * 4 + r) * HD + qc8;
        const float* qp = g_qkv + (size_t)(b * 16 + s) * QKV_N + hcol;
        float4 q0 = *(const float4*)(qp);
        float4 q1 = *(const float4*)(qp + 4);
        float4 b0 = *(const float4*)(bq + hcol);
        float4 b1 = *(const float4*)(bq + hcol + 4);
        q0.x = (q0.x + b0.x) * scale; q0.y = (q0.y + b0.y) * scale;
        q0.z = (q0.z + b0.z) * scale; q0.w = (q0.w + b0.w) * scale;
        q1.x = (q1.x + b1.x) * scale; q1.y = (q1.y + b1.y) * scale;
        q1.z = (q1.z + b1.z) * scale; q1.w = (q1.w + b1.w) * scale;
        *(uint4*)(&Qs[m * 136 + qc8]) = f8h8(q0, q1);
    }
    if (tid < 64) rowsum[tid] = 0.f;

    HC acc_o[2];
#pragma unroll
    for (int j = 0; j < 2; j++) wmma::fill_fragment(acc_o[j], 0.0f);

    const int row = tid & 63, qq = tid >> 6;

#define STAGE_KV(l0, qoff, cache, bias)                                            \
    _Pragma("unroll")                                                              \
    for (int i = 0; i < 4; i++) {                                                  \
        int slot = tid + i * 512;                                                  \
        int l = slot >> 4;                                                         \
        int c8 = (slot & 15) << 3;                                                 \
        int lg = (l0) + l;                                                         \
        float4 c0, c1;                                                             \
        if (lg >= STARTP) {                                                        \
            const float* sp_ = g_qkv + (size_t)(b * 16 + (lg - STARTP)) * QKV_N    \
                               + (qoff) + g * HD + c8;                             \
            c0 = *(const float4*)(sp_); c1 = *(const float4*)(sp_ + 4);            \
            float4 b0 = *(const float4*)((bias) + g * HD + c8);                    \
            float4 b1 = *(const float4*)((bias) + g * HD + c8 + 4);                \
            c0.x += b0.x; c0.y += b0.y; c0.z += b0.z; c0.w += b0.w;                \
            c1.x += b1.x; c1.y += b1.y; c1.z += b1.z; c1.w += b1.w;                \
        } else {                                                                   \
            const float* sp_ = (cache) + (((size_t)b * MAXSEQ + lg) * NKV + g) * HD + c8; \
            c0 = *(const float4*)(sp_); c1 = *(const float4*)(sp_ + 4);            \
        }                                                                          \
        *(uint4*)(&KVs[l * 136 + c8]) = f8h8(c0, c1);                              \
    }

    const int lbase0 = split * KVSPLIT;

    for (int t = 0; t < NT_FL; t++) {
        const int l0 = lbase0 + t * LT;

        STAGE_KV(l0, 4096, k_cache, bk)
        __syncthreads();

        // S = Q @ K^T (log2 domain) : 64x128, k=128; warp tile 16x32
        HC acc_s[2];
        wmma::fill_fragment(acc_s[0], 0.0f);
        wmma::fill_fragment(acc_s[1], 0.0f);
#pragma unroll
        for (int kk = 0; kk < HD; kk += 16) {
            HA a;
            wmma::load_matrix_sync(a, Qs + (wr4 * 16) * 136 + kk, 136);
#pragma unroll
            for (int j = 0; j < 2; j++) {
                HBT bt;
                wmma::load_matrix_sync(bt, KVs + (wc4 * 32 + j * 16) * 136 + kk, 136);
                wmma::mma_sync(acc_s[j], a, bt, acc_s[j]);
            }
        }
        // exp in registers (fp32 input), convert to half fragment, store to Ps
        HCH ph[2];
#pragma unroll
        for (int j = 0; j < 2; j++) {
#pragma unroll
            for (int e = 0; e < acc_s[j].num_elements; e++)
                ph[j].x[e] = __float2half(ex2f(acc_s[j].x[e]));
            wmma::store_matrix_sync(Ps + (wr4 * 16) * 136 + wc4 * 32 + j * 16,
                                    ph[j], 136, wmma::mem_row_major);
        }
        __syncthreads();   // KVs reads done; Ps visible

        STAGE_KV(l0, 5120, v_cache, bv)       // V into KVs
        {
            const uint4 p0 = *(const uint4*)(&Ps[row * 136 + qq * 16]);
            const uint4 p1 = *(const uint4*)(&Ps[row * 136 + qq * 16 + 8]);
            const uint32_t w[8] = {p0.x, p0.y, p0.z, p0.w, p1.x, p1.y, p1.z, p1.w};
            float part = 0.f;
#pragma unroll
            for (int j = 0; j < 8; j++) {
                float2 f = __half22float2(*(const __half2*)&w[j]);
                part += f.x + f.y;
            }
            tmp[qq * 64 + row] = part;
        }
        __syncthreads();

        if (tid < 64) {
            float s = 0.f;
#pragma unroll
            for (int q8 = 0; q8 < 8; q8++) s += tmp[q8 * 64 + tid];
            rowsum[tid] += s;
        }

        // O += P @ V : 64x128, k=128; warp tile 16x32
#pragma unroll
        for (int kk = 0; kk < LT; kk += 16) {
            HA a;
            wmma::load_matrix_sync(a, Ps + (wr4 * 16) * 136 + kk, 136);
#pragma unroll
            for (int j = 0; j < 2; j++) {
                HB bfr;
                wmma::load_matrix_sync(bfr, KVs + kk * 136 + wc4 * 32 + j * 16, 136);
                wmma::mma_sync(acc_o[j], a, bfr, acc_o[j]);
            }
        }
        __syncthreads();
    }

#pragma unroll
    for (int j = 0; j < 2; j++)
        wmma::store_matrix_sync(
            g_pvp + ((size_t)(split * NBG + bg) * 64 + wr4 * 16) * HD + wc4 * 32 + j * 16,
            acc_o[j], HD, wmma::mem_row_major);
    if (tid < 64)
        g_rsum[(size_t)(split * NBG + bg) * 64 + tid] = rowsum[tid];
}

// ---------------- combine splits, normalize, remap -----------------------------
__global__ void flash_combine_kernel()
{
    int t = blockIdx.x * 256 + threadIdx.x;
    int rowg = t >> 5;
    int c4 = (t & 31) << 2;
    float4 s = make_float4(0.f, 0.f, 0.f, 0.f);
    float den = 0.f;
#pragma unroll
    for (int sp = 0; sp < NSPLIT; sp++) {
        float4 v = *(const float4*)(g_pvp + ((size_t)sp * NBG * 64 + rowg) * HD + c4);
        s.x += v.x; s.y += v.y; s.z += v.z; s.w += v.w;
        den += g_rsum[(size_t)sp * NBG * 64 + rowg];
    }
    float inv = 1.f / den;
    s.x *= inv; s.y *= inv; s.z *= inv; s.w *= inv;
    int bg = rowg >> 6, qr = rowg & 63;
    int b = bg >> 3, g = bg & 7, r = qr >> 4, sq = qr & 15;
    *(float4*)(g_att + (size_t)(b * 16 + sq) * DIM + (g * 4 + r) * HD + c4) = s;
}

// ---------------- kernel 4: O projection split-K(8), N-tile 256 ----------------
__global__ void __launch_bounds__(NTHR) o_kernel(const float* __restrict__ Wo)
{
    const int n0 = blockIdx.x * 256;
    const int kb = blockIdx.y * (DIM / SPLITO);
    const float* Abase = g_att + kb;
    const float* Bbase = Wo + (size_t)kb * DIM + n0;
    float* Cpart = g_op + (size_t)blockIdx.y * TOK * DIM + n0;
    GEMM_BODY(Abase, DIM, Bbase, DIM, Cpart, DIM, DIM / SPLITO / 32)
}

__global__ void o_reduce_kernel(float* __restrict__ out, const float* __restrict__ bo)
{
    int i4 = (blockIdx.x * 256 + threadIdx.x) * 4;
    int n = i4 & (DIM - 1);
    float4 s = *(const float4*)(bo + n);
#pragma unroll
    for (int sp = 0; sp < SPLITO; sp++) {
        float4 v = *(const float4*)(g_op + (size_t)sp * TOK * DIM + i4);
        s.x += v.x; s.y += v.y; s.z += v.z; s.w += v.w;
    }
    *(float4*)(out + i4) = s;
}

// ---------------- launch ----------------------------------------------------------
extern "C" void kernel_launch(void* const* d_in, const int* in_sizes, int n_in,
                              void* d_out, int out_size)
{
    const float* x  = (const float*)d_in[0];
    const float* kc = (const float*)d_in[1];
    const float* vc = (const float*)d_in[2];
    const float* Wq = (const float*)d_in[3];  const float* bq = (const float*)d_in[4];
    const float* Wk = (const float*)d_in[5];  const float* bk = (const float*)d_in[6];
    const float* Wv = (const float*)d_in[7];  const float* bv = (const float*)d_in[8];
    const float* Wo = (const float*)d_in[9];  const float* bo = (const float*)d_in[10];
    float* out = (float*)d_out;

    cudaFuncSetAttribute(flash_kernel,
                         cudaFuncAttributeMaxDynamicSharedMemorySize, SMEM_FLASH);
    cudaFuncSetAttribute(qkv_kernel,
                         cudaFuncAttributeMaxDynamicSharedMemorySize, SMEM_GEMM);
    cudaFuncSetAttribute(o_kernel,
                         cudaFuncAttributeMaxDynamicSharedMemorySize, SMEM_GEMM);

    qkv_kernel<<<dim3(24, SPLITQ), NTHR, SMEM_GEMM>>>(x, Wq, Wk, Wv);
    qkv_reduce_kernel<<<TOK * QKV_N / 1024, 256>>>();
    flash_kernel<<<dim3(NSPLIT, NBG), NTHR, SMEM_FLASH>>>(kc, vc, bq, bk, bv);
    flash_combine_kernel<<<512, 256>>>();
    o_kernel<<<dim3(16, SPLITO), NTHR, SMEM_GEMM>>>(Wo);
    o_reduce_kernel<<<512, 256>>>(out, bo);
}

// round 17
// speedup vs baseline: 1.1801x; 1.0581x over previous
#include <cuda_runtime.h>
#include <cuda_fp16.h>
#include <mma.h>
#include <math.h>
#include <cstdint>

using namespace nvcuda;

#define BSZ     8
#define QL      16
#define TOK     128
#define DIM     4096
#define NKV     8
#define HD      128
#define MAXSEQ  4096
#define STARTP  4080
#define KVLEN   4096
#define QKV_N   6144
#define NBG     64
#define NSPLIT  4
#define KVSPLIT 1024
#define LT      128
#define NT_FL   (KVSPLIT / LT)
#define SPLITQ  16
#define SPLITO  8
#define NTHR    512

__device__ float g_qkv[TOK * QKV_N];
__device__ float g_qkvp[SPLITQ * TOK * QKV_N];
__device__ float g_op[SPLITO * TOK * DIM];
__device__ float g_pvp[NSPLIT * NBG * 64 * HD];
__device__ float g_rsum[NSPLIT * NBG * 64];
__device__ float g_att[TOK * DIM];

typedef wmma::fragment<wmma::accumulator, 16, 16, 16, float> HC;
typedef wmma::fragment<wmma::accumulator, 16, 16, 16, __half> HCH;
typedef wmma::fragment<wmma::matrix_a, 16, 16, 16, __half, wmma::row_major> HA;
typedef wmma::fragment<wmma::matrix_b, 16, 16, 16, __half, wmma::row_major> HB;
typedef wmma::fragment<wmma::matrix_b, 16, 16, 16, __half, wmma::col_major> HBT;

__device__ __forceinline__ uint4 f8h8(float4 a, float4 b) {
    __half2 h0 = __floats2half2_rn(a.x, a.y);
    __half2 h1 = __floats2half2_rn(a.z, a.w);
    __half2 h2 = __floats2half2_rn(b.x, b.y);
    __half2 h3 = __floats2half2_rn(b.z, b.w);
    uint4 r;
    r.x = *(uint32_t*)&h0; r.y = *(uint32_t*)&h1;
    r.z = *(uint32_t*)&h2; r.w = *(uint32_t*)&h3;
    return r;
}

__device__ __forceinline__ float ex2f(float x) {
    float r;
    asm("ex2.approx.f32 %0, %1;" : "=f"(r) : "f"(x));
    return r;
}

// ------------- 128x256 split-K fp16 GEMM body, 512 thr, warp 32x64 -------------
#define SMEM_GEMM (2 * 128 * 40 * 2 + 2 * 32 * 264 * 2)

#define GEMM_BODY(Abase, LDAG, Bbase, LDBG, CPART, LDC, NCHUNK)                    \
    extern __shared__ __half smg[];                                                \
    __half* Asb[2] = {smg, smg + 128 * 40};                                        \
    __half* Bsb[2] = {smg + 2 * 128 * 40, smg + 2 * 128 * 40 + 32 * 264};          \
    const int tid = threadIdx.x;                                                   \
    const int wid = tid >> 5, wr = wid >> 2, wcx = wid & 3;                        \
    const int am = tid >> 2, ak = (tid & 3) << 3;                                  \
    const int bs0 = tid, bs1 = tid + 512;                                          \
    const int br0 = bs0 >> 5, bc0 = (bs0 & 31) << 3;                               \
    const int br1 = bs1 >> 5, bc1 = (bs1 & 31) << 3;                               \
    HC acc[2][4];                                                                  \
    _Pragma("unroll")                                                              \
    for (int i = 0; i < 2; i++)                                                    \
        _Pragma("unroll")                                                          \
        for (int j = 0; j < 4; j++) wmma::fill_fragment(acc[i][j], 0.0f);          \
    float4 ra0, ra1, rb00, rb01, rb10, rb11;                                       \
    ra0 = *(const float4*)((Abase) + (size_t)am * (LDAG) + ak);                    \
    ra1 = *(const float4*)((Abase) + (size_t)am * (LDAG) + ak + 4);                \
    rb00 = *(const float4*)((Bbase) + (size_t)br0 * (LDBG) + bc0);                 \
    rb01 = *(const float4*)((Bbase) + (size_t)br0 * (LDBG) + bc0 + 4);             \
    rb10 = *(const float4*)((Bbase) + (size_t)br1 * (LDBG) + bc1);                 \
    rb11 = *(const float4*)((Bbase) + (size_t)br1 * (LDBG) + bc1 + 4);             \
    *(uint4*)(&Asb[0][am * 40 + ak]) = f8h8(ra0, ra1);                             \
    *(uint4*)(&Bsb[0][br0 * 264 + bc0]) = f8h8(rb00, rb01);                        \
    *(uint4*)(&Bsb[0][br1 * 264 + bc1]) = f8h8(rb10, rb11);                        \
    __syncthreads();                                                               \
    for (int t = 0; t < (NCHUNK); t++) {                                           \
        int cur = t & 1;                                                           \
        if (t + 1 < (NCHUNK)) {                                                    \
            ra0 = *(const float4*)((Abase) + (size_t)am * (LDAG) + (t + 1) * 32 + ak); \
            ra1 = *(const float4*)((Abase) + (size_t)am * (LDAG) + (t + 1) * 32 + ak + 4); \
            rb00 = *(const float4*)((Bbase) + (size_t)((t + 1) * 32 + br0) * (LDBG) + bc0); \
            rb01 = *(const float4*)((Bbase) + (size_t)((t + 1) * 32 + br0) * (LDBG) + bc0 + 4); \
            rb10 = *(const float4*)((Bbase) + (size_t)((t + 1) * 32 + br1) * (LDBG) + bc1); \
            rb11 = *(const float4*)((Bbase) + (size_t)((t + 1) * 32 + br1) * (LDBG) + bc1 + 4); \
        }                                                                          \
        _Pragma("unroll")                                                          \
        for (int kk = 0; kk < 32; kk += 16) {                                      \
            HA a[2];                                                               \
            _Pragma("unroll")                                                      \
            for (int i = 0; i < 2; i++)                                            \
                wmma::load_matrix_sync(a[i], Asb[cur] + (wr * 32 + i * 16) * 40 + kk, 40); \
            _Pragma("unroll")                                                      \
            for (int j = 0; j < 4; j++) {                                          \
                HB b;                                                              \
                wmma::load_matrix_sync(b, Bsb[cur] + kk * 264 + wcx * 64 + j * 16, 264); \
                wmma::mma_sync(acc[0][j], a[0], b, acc[0][j]);                     \
                wmma::mma_sync(acc[1][j], a[1], b, acc[1][j]);                     \
            }                                                                      \
        }                                                                          \
        if (t + 1 < (NCHUNK)) {                                                    \
            *(uint4*)(&Asb[1 - cur][am * 40 + ak]) = f8h8(ra0, ra1);               \
            *(uint4*)(&Bsb[1 - cur][br0 * 264 + bc0]) = f8h8(rb00, rb01);          \
            *(uint4*)(&Bsb[1 - cur][br1 * 264 + bc1]) = f8h8(rb10, rb11);          \
        }                                                                          \
        __syncthreads();                                                           \
    }                                                                              \
    _Pragma("unroll")                                                              \
    for (int i = 0; i < 2; i++)                                                    \
        _Pragma("unroll")                                                          \
        for (int j = 0; j < 4; j++)                                                \
            wmma::store_matrix_sync((CPART) + (size_t)(wr * 32 + i * 16) * (LDC) + wcx * 64 + j * 16, \
                                    acc[i][j], (LDC), wmma::mem_row_major);

// ---------------- kernel 1: QKV GEMM split-K(16), N-tile 256 -------------------
__global__ void __launch_bounds__(NTHR) qkv_kernel(
    const float* __restrict__ x,
    const float* __restrict__ Wq, const float* __restrict__ Wk,
    const float* __restrict__ Wv)
{
    const int n0 = blockIdx.x * 256;
    const int kb = blockIdx.y * (DIM / SPLITQ);
    const float* B; int ldb, col;
    if (n0 < 4096)      { B = Wq; ldb = 4096; col = n0; }
    else if (n0 < 5120) { B = Wk; ldb = 1024; col = n0 - 4096; }
    else                { B = Wv; ldb = 1024; col = n0 - 5120; }

    const float* Abase = x + kb;
    const float* Bbase = B + (size_t)kb * ldb + col;
    float* Cpart = g_qkvp + (size_t)blockIdx.y * TOK * QKV_N + n0;
    GEMM_BODY(Abase, DIM, Bbase, ldb, Cpart, QKV_N, DIM / SPLITQ / 32)
}

__global__ void qkv_reduce_kernel()
{
    int i4 = (blockIdx.x * 256 + threadIdx.x) * 4;
    float4 s = make_float4(0.f, 0.f, 0.f, 0.f);
#pragma unroll
    for (int sp = 0; sp < SPLITQ; sp++) {
        float4 v = *(const float4*)(g_qkvp + (size_t)sp * TOK * QKV_N + i4);
        s.x += v.x; s.y += v.y; s.z += v.z; s.w += v.w;
    }
    *(float4*)(g_qkv + i4) = s;
}

// ---------------- kernel 2: flash attention fp16 (R13 structure, verbatim) -----
#define SMEM_FLASH ((64*136 + 128*136 + 64*136) * 2 + (64 + 512) * 4)

__global__ void __launch_bounds__(NTHR, 2) flash_kernel(
    const float* __restrict__ k_cache, const float* __restrict__ v_cache,
    const float* __restrict__ bq, const float* __restrict__ bk,
    const float* __restrict__ bv)
{
    extern __shared__ char smc[];
    __half* Qs   = (__half*)smc;                          // [64][136]
    __half* KVs  = Qs + 64 * 136;                         // [128][136]
    __half* Ps   = KVs + 128 * 136;                       // [64][136]
    float* rowsum = (float*)(Ps + 64 * 136);              // [64]
    float* tmp    = rowsum + 64;                          // [8][64]

    const int split = blockIdx.x;
    const int bg = blockIdx.y, b = bg >> 3, g = bg & 7;
    const int tid = threadIdx.x, wid = tid >> 5;
    const int wr4 = wid >> 2, wc4 = wid & 3;
    const float scale = 0.08838834764831845f * 1.4426950408889634f;  // log2 domain

    const int qm0 = tid >> 4;
    const int qc8 = (tid & 15) << 3;
#pragma unroll
    for (int i = 0; i < 2; i++) {
        int m = qm0 + 32 * i;
        int r = m >> 4, s = m & 15;
        int hcol = (g * 4 + r) * HD + qc8;
        const float* qp = g_qkv + (size_t)(b * 16 + s) * QKV_N + hcol;
        float4 q0 = *(const float4*)(qp);
        float4 q1 = *(const float4*)(qp + 4);
        float4 b0 = *(const float4*)(bq + hcol);
        float4 b1 = *(const float4*)(bq + hcol + 4);
        q0.x = (q0.x + b0.x) * scale; q0.y = (q0.y + b0.y) * scale;
        q0.z = (q0.z + b0.z) * scale; q0.w = (q0.w + b0.w) * scale;
        q1.x = (q1.x + b1.x) * scale; q1.y = (q1.y + b1.y) * scale;
        q1.z = (q1.z + b1.z) * scale; q1.w = (q1.w + b1.w) * scale;
        *(uint4*)(&Qs[m * 136 + qc8]) = f8h8(q0, q1);
    }
    if (tid < 64) rowsum[tid] = 0.f;

    HC acc_o[2];
#pragma unroll
    for (int j = 0; j < 2; j++) wmma::fill_fragment(acc_o[j], 0.0f);

    const int row = tid & 63, qq = tid >> 6;

#define STAGE_KV(l0, qoff, cache, bias)                                            \
    _Pragma("unroll")                                                              \
    for (int i = 0; i < 4; i++) {                                                  \
        int slot = tid + i * 512;                                                  \
        int l = slot >> 4;                                                         \
        int c8 = (slot & 15) << 3;                                                 \
        int lg = (l0) + l;                                                         \
        float4 c0, c1;                                                             \
        if (lg >= STARTP) {                                                        \
            const float* sp_ = g_qkv + (size_t)(b * 16 + (lg - STARTP)) * QKV_N    \
                               + (qoff) + g * HD + c8;                             \
            c0 = *(const float4*)(sp_); c1 = *(const float4*)(sp_ + 4);            \
            float4 b0 = *(const float4*)((bias) + g * HD + c8);                    \
            float4 b1 = *(const float4*)((bias) + g * HD + c8 + 4);                \
            c0.x += b0.x; c0.y += b0.y; c0.z += b0.z; c0.w += b0.w;                \
            c1.x += b1.x; c1.y += b1.y; c1.z += b1.z; c1.w += b1.w;                \
        } else {                                                                   \
            const float* sp_ = (cache) + (((size_t)b * MAXSEQ + lg) * NKV + g) * HD + c8; \
            c0 = *(const float4*)(sp_); c1 = *(const float4*)(sp_ + 4);            \
        }                                                                          \
        *(uint4*)(&KVs[l * 136 + c8]) = f8h8(c0, c1);                              \
    }

    const int lbase0 = split * KVSPLIT;

    for (int t = 0; t < NT_FL; t++) {
        const int l0 = lbase0 + t * LT;

        STAGE_KV(l0, 4096, k_cache, bk)
        __syncthreads();

        // S = Q @ K^T (log2 domain) : 64x128, k=128; warp tile 16x32
        HC acc_s[2];
        wmma::fill_fragment(acc_s[0], 0.0f);
        wmma::fill_fragment(acc_s[1], 0.0f);
#pragma unroll
        for (int kk = 0; kk < HD; kk += 16) {
            HA a;
            wmma::load_matrix_sync(a, Qs + (wr4 * 16) * 136 + kk, 136);
#pragma unroll
            for (int j = 0; j < 2; j++) {
                HBT bt;
                wmma::load_matrix_sync(bt, KVs + (wc4 * 32 + j * 16) * 136 + kk, 136);
                wmma::mma_sync(acc_s[j], a, bt, acc_s[j]);
            }
        }
        // exp in registers (fp32 input), convert to half fragment, store to Ps
        HCH ph[2];
#pragma unroll
        for (int j = 0; j < 2; j++) {
#pragma unroll
            for (int e = 0; e < acc_s[j].num_elements; e++)
                ph[j].x[e] = __float2half(ex2f(acc_s[j].x[e]));
            wmma::store_matrix_sync(Ps + (wr4 * 16) * 136 + wc4 * 32 + j * 16,
                                    ph[j], 136, wmma::mem_row_major);
        }
        __syncthreads();   // KVs reads done; Ps visible

        STAGE_KV(l0, 5120, v_cache, bv)       // V into KVs
        {
            const uint4 p0 = *(const uint4*)(&Ps[row * 136 + qq * 16]);
            const uint4 p1 = *(const uint4*)(&Ps[row * 136 + qq * 16 + 8]);
            const uint32_t w[8] = {p0.x, p0.y, p0.z, p0.w, p1.x, p1.y, p1.z, p1.w};
            float part = 0.f;
#pragma unroll
            for (int j = 0; j < 8; j++) {
                float2 f = __half22float2(*(const __half2*)&w[j]);
                part += f.x + f.y;
            }
            tmp[qq * 64 + row] = part;
        }
        __syncthreads();

        if (tid < 64) {
            float s = 0.f;
#pragma unroll
            for (int q8 = 0; q8 < 8; q8++) s += tmp[q8 * 64 + tid];
            rowsum[tid] += s;
        }

        // O += P @ V : 64x128, k=128; warp tile 16x32
#pragma unroll
        for (int kk = 0; kk < LT; kk += 16) {
            HA a;
            wmma::load_matrix_sync(a, Ps + (wr4 * 16) * 136 + kk, 136);
#pragma unroll
            for (int j = 0; j < 2; j++) {
                HB bfr;
                wmma::load_matrix_sync(bfr, KVs + kk * 136 + wc4 * 32 + j * 16, 136);
                wmma::mma_sync(acc_o[j], a, bfr, acc_o[j]);
            }
        }
        __syncthreads();
    }

#pragma unroll
    for (int j = 0; j < 2; j++)
        wmma::store_matrix_sync(
            g_pvp + ((size_t)(split * NBG + bg) * 64 + wr4 * 16) * HD + wc4 * 32 + j * 16,
            acc_o[j], HD, wmma::mem_row_major);
    if (tid < 64)
        g_rsum[(size_t)(split * NBG + bg) * 64 + tid] = rowsum[tid];
}

// ---------------- combine splits, normalize, remap -----------------------------
__global__ void flash_combine_kernel()
{
    int t = blockIdx.x * 256 + threadIdx.x;
    int rowg = t >> 5;
    int c4 = (t & 31) << 2;
    float4 s = make_float4(0.f, 0.f, 0.f, 0.f);
    float den = 0.f;
#pragma unroll
    for (int sp = 0; sp < NSPLIT; sp++) {
        float4 v = *(const float4*)(g_pvp + ((size_t)sp * NBG * 64 + rowg) * HD + c4);
        s.x += v.x; s.y += v.y; s.z += v.z; s.w += v.w;
        den += g_rsum[(size_t)sp * NBG * 64 + rowg];
    }
    float inv = 1.f / den;
    s.x *= inv; s.y *= inv; s.z *= inv; s.w *= inv;
    int bg = rowg >> 6, qr = rowg & 63;
    int b = bg >> 3, g = bg & 7, r = qr >> 4, sq = qr & 15;
    *(float4*)(g_att + (size_t)(b * 16 + sq) * DIM + (g * 4 + r) * HD + c4) = s;
}

// ---------------- kernel 4: O projection split-K(8), N-tile 256 ----------------
__global__ void __launch_bounds__(NTHR) o_kernel(const float* __restrict__ Wo)
{
    const int n0 = blockIdx.x * 256;
    const int kb = blockIdx.y * (DIM / SPLITO);
    const float* Abase = g_att + kb;
    const float* Bbase = Wo + (size_t)kb * DIM + n0;
    float* Cpart = g_op + (size_t)blockIdx.y * TOK * DIM + n0;
    GEMM_BODY(Abase, DIM, Bbase, DIM, Cpart, DIM, DIM / SPLITO / 32)
}

__global__ void o_reduce_kernel(float* __restrict__ out, const float* __restrict__ bo)
{
    int i4 = (blockIdx.x * 256 + threadIdx.x) * 4;
    int n = i4 & (DIM - 1);
    float4 s = *(const float4*)(bo + n);
#pragma unroll
    for (int sp = 0; sp < SPLITO; sp++) {
        float4 v = *(const float4*)(g_op + (size_t)sp * TOK * DIM + i4);
        s.x += v.x; s.y += v.y; s.z += v.z; s.w += v.w;
    }
    *(float4*)(out + i4) = s;
}

// ---------------- launch ----------------------------------------------------------
extern "C" void kernel_launch(void* const* d_in, const int* in_sizes, int n_in,
                              void* d_out, int out_size)
{
    const float* x  = (const float*)d_in[0];
    const float* kc = (const float*)d_in[1];
    const float* vc = (const float*)d_in[2];
    const float* Wq = (const float*)d_in[3];  const float* bq = (const float*)d_in[4];
    const float* Wk = (const float*)d_in[5];  const float* bk = (const float*)d_in[6];
    const float* Wv = (const float*)d_in[7];  const float* bv = (const float*)d_in[8];
    const float* Wo = (const float*)d_in[9];  const float* bo = (const float*)d_in[10];
    float* out = (float*)d_out;

    cudaFuncSetAttribute(flash_kernel,
                         cudaFuncAttributeMaxDynamicSharedMemorySize, SMEM_FLASH);
    cudaFuncSetAttribute(qkv_kernel,
                         cudaFuncAttributeMaxDynamicSharedMemorySize, SMEM_GEMM);
    cudaFuncSetAttribute(o_kernel,
                         cudaFuncAttributeMaxDynamicSharedMemorySize, SMEM_GEMM);

    qkv_kernel<<<dim3(24, SPLITQ), NTHR, SMEM_GEMM>>>(x, Wq, Wk, Wv);
    qkv_reduce_kernel<<<TOK * QKV_N / 1024, 256>>>();
    flash_kernel<<<dim3(NSPLIT, NBG), NTHR, SMEM_FLASH>>>(kc, vc, bq, bk, bv);
    flash_combine_kernel<<<512, 256>>>();
    o_kernel<<<dim3(16, SPLITO), NTHR, SMEM_GEMM>>>(Wo);
    o_reduce_kernel<<<512, 256>>>(out, bo);
}